// round 3
// baseline (speedup 1.0000x reference)
#include <cuda_runtime.h>
#include <cuda_bf16.h>
#include <math.h>

// Problem constants
#define B_SZ   8
#define L_SEQ  4096
#define D_MODEL 512
#define NC     128      // chunks
#define CS     4        // chunk size
#define NSTATE 64
#define NTAPS  32       // e^{-0.5*32} ~ 1e-7 -> truncation negligible vs 1e-3 tol
#define M_ROWS (B_SZ * L_SEQ)   // 32768

// Scratch (device globals; no cudaMalloc allowed)
__device__ float g_z [M_ROWS * D_MODEL];   // layernorm output
__device__ float g_z1[M_ROWS * D_MODEL];   // in-proj output
__device__ float g_y [M_ROWS * D_MODEL];   // FIR output
__device__ float g_k [NC * NTAPS];         // FIR taps

// ---------------------------------------------------------------------------
// Tap generation: k[c,tau] = sum_n exp(re*tau) * (CBre*cos(im*tau) - CBim*sin(im*tau))
// ---------------------------------------------------------------------------
__global__ void kgen_kernel(const float* __restrict__ lre, const float* __restrict__ lim,
                            const float* __restrict__ Bm,  const float* __restrict__ cre,
                            const float* __restrict__ cim)
{
    int c = blockIdx.x;          // 0..127
    int tau = threadIdx.x;       // 0..31
    float ft = (float)tau;
    float acc = 0.0f;
    #pragma unroll 8
    for (int n = 0; n < NSTATE; n++) {
        int idx = c * NSTATE + n;
        float re = lre[idx];
        float im = lim[idx];
        float bn = Bm[idx];
        float cr = cre[idx] * bn;
        float ci = cim[idx] * bn;
        float ang = im * ft;
        float s, co;
        sincosf(ang, &s, &co);
        acc += expf(re * ft) * (cr * co - ci * s);
    }
    g_k[c * NTAPS + tau] = acc;
}

// ---------------------------------------------------------------------------
// LayerNorm: one block per row of 512
// ---------------------------------------------------------------------------
__global__ void ln_kernel(const float* __restrict__ x, const float* __restrict__ gamma,
                          const float* __restrict__ beta)
{
    int row = blockIdx.x;
    int tid = threadIdx.x;      // 128 threads, each owns a float4 (512 elems)
    const float4* xr = (const float4*)(x + (size_t)row * D_MODEL);
    float4 v = xr[tid];
    float s  = v.x + v.y + v.z + v.w;
    float sq = v.x*v.x + v.y*v.y + v.z*v.z + v.w*v.w;

    // warp reduce
    #pragma unroll
    for (int off = 16; off > 0; off >>= 1) {
        s  += __shfl_xor_sync(0xFFFFFFFFu, s,  off);
        sq += __shfl_xor_sync(0xFFFFFFFFu, sq, off);
    }
    __shared__ float ss[4], ssq[4];
    int warp = tid >> 5, lane = tid & 31;
    if (lane == 0) { ss[warp] = s; ssq[warp] = sq; }
    __syncthreads();
    float tots  = ss[0] + ss[1] + ss[2] + ss[3];
    float totsq = ssq[0] + ssq[1] + ssq[2] + ssq[3];

    float mu  = tots * (1.0f / D_MODEL);
    float var = totsq * (1.0f / D_MODEL) - mu * mu;
    float inv = rsqrtf(var + 1e-5f);

    float4 gg = ((const float4*)gamma)[tid];
    float4 bb = ((const float4*)beta)[tid];
    float4 o;
    o.x = (v.x - mu) * inv * gg.x + bb.x;
    o.y = (v.y - mu) * inv * gg.y + bb.y;
    o.z = (v.z - mu) * inv * gg.z + bb.z;
    o.w = (v.w - mu) * inv * gg.w + bb.w;
    ((float4*)(g_z + (size_t)row * D_MODEL))[tid] = o;
}

// ---------------------------------------------------------------------------
// SGEMM: C[M,N] = A[M,K] @ W[K,N] + bias  (+ optional gelu+residual)
// M=32768, N=K=512. BM=BN=128, BK=8, 256 threads, 8x8 per thread.
// ---------------------------------------------------------------------------
__device__ __forceinline__ float gelu_exact(float v) {
    return 0.5f * v * (1.0f + erff(v * 0.70710678118654752f));
}

template<int EPI>   // 0: bias only ; 1: bias + gelu + residual
__global__ __launch_bounds__(256, 2)
void sgemm_kernel(const float* __restrict__ A, const float* __restrict__ W,
                  const float* __restrict__ bias, const float* __restrict__ resid,
                  float* __restrict__ C)
{
    const int K = 512, N = 512;
    __shared__ float As[8][128];
    __shared__ float Bs[8][128];

    int tid = threadIdx.x;
    int bm = blockIdx.y;   // 0..255
    int bn = blockIdx.x;   // 0..3

    int aRow = tid >> 1;           // 0..127
    int aCol = (tid & 1) * 4;      // 0 or 4
    int bRow = tid >> 5;           // 0..7
    int bCol = (tid & 31) * 4;     // 0..124

    const float* Ap = A + ((size_t)bm * 128 + aRow) * K + aCol;
    const float* Bp = W + (size_t)bRow * N + bn * 128 + bCol;

    int ty = tid >> 4, tx = tid & 15;

    float acc[8][8];
    #pragma unroll
    for (int i = 0; i < 8; i++)
        #pragma unroll
        for (int j = 0; j < 8; j++) acc[i][j] = 0.0f;

    float4 a4 = *(const float4*)Ap;
    float4 b4 = *(const float4*)Bp;

    for (int k0 = 0; k0 < K; k0 += 8) {
        As[aCol + 0][aRow] = a4.x;
        As[aCol + 1][aRow] = a4.y;
        As[aCol + 2][aRow] = a4.z;
        As[aCol + 3][aRow] = a4.w;
        *(float4*)&Bs[bRow][bCol] = b4;
        __syncthreads();

        if (k0 + 8 < K) {
            a4 = *(const float4*)(Ap + k0 + 8);
            b4 = *(const float4*)(Bp + (size_t)(k0 + 8) * N);
        }

        #pragma unroll
        for (int kk = 0; kk < 8; kk++) {
            float ra[8], rb[8];
            #pragma unroll
            for (int i = 0; i < 8; i++) ra[i] = As[kk][ty * 8 + i];
            #pragma unroll
            for (int j = 0; j < 8; j++) rb[j] = Bs[kk][tx * 8 + j];
            #pragma unroll
            for (int i = 0; i < 8; i++)
                #pragma unroll
                for (int j = 0; j < 8; j++)
                    acc[i][j] += ra[i] * rb[j];
        }
        __syncthreads();
    }

    // epilogue
    #pragma unroll
    for (int i = 0; i < 8; i++) {
        size_t row = (size_t)bm * 128 + ty * 8 + i;
        #pragma unroll
        for (int j = 0; j < 8; j++) {
            int col = bn * 128 + tx * 8 + j;
            float v = acc[i][j] + bias[col];
            if (EPI == 1) {
                v = resid[row * N + col] + gelu_exact(v);
            }
            C[row * N + col] = v;
        }
    }
}

// ---------------------------------------------------------------------------
// Bidirectional 32-tap FIR + D skip, per (b, chunk), float4 over chunk-size.
// y[t] = D*u[t] + sum_tau k[tau]*(u[t-tau] + u[t+1+tau])   (zero-padded in [0,L))
// Layout: u viewed as float4[(b*L + t)*NC + c]
// ---------------------------------------------------------------------------
__global__ void fir_kernel(const float* __restrict__ Dvec)
{
    int c  = blockIdx.y;      // 0..127
    int b  = blockIdx.z;      // 0..7
    int t0 = blockIdx.x * 128;
    int tid = threadIdx.x;    // 128

    const float4* u4 = (const float4*)g_z1;
    __shared__ float4 su[191];   // [t0-31 .. t0+159]
    __shared__ float  sk[NTAPS];

    for (int i = tid; i < 191; i += 128) {
        int t = t0 - 31 + i;
        float4 v = make_float4(0.f, 0.f, 0.f, 0.f);
        if (t >= 0 && t < L_SEQ) v = u4[((size_t)b * L_SEQ + t) * NC + c];
        su[i] = v;
    }
    if (tid < NTAPS) sk[tid] = g_k[c * NTAPS + tid];
    __syncthreads();

    float dv = Dvec[c];
    float4 cen = su[tid + 31];
    float4 acc;
    acc.x = dv * cen.x;
    acc.y = dv * cen.y;
    acc.z = dv * cen.z;
    acc.w = dv * cen.w;

    #pragma unroll
    for (int tau = 0; tau < NTAPS; tau++) {
        float kt = sk[tau];
        float4 a  = su[tid + 31 - tau];   // forward  u[t - tau]
        float4 bb = su[tid + 32 + tau];   // backward u[t + 1 + tau]
        acc.x += kt * (a.x + bb.x);
        acc.y += kt * (a.y + bb.y);
        acc.z += kt * (a.z + bb.z);
        acc.w += kt * (a.w + bb.w);
    }

    ((float4*)g_y)[((size_t)b * L_SEQ + t0 + tid) * NC + c] = acc;
}

// ---------------------------------------------------------------------------
// Launch
// ---------------------------------------------------------------------------
extern "C" void kernel_launch(void* const* d_in, const int* in_sizes, int n_in,
                              void* d_out, int out_size)
{
    const float* x       = (const float*)d_in[0];
    const float* ln_g    = (const float*)d_in[1];
    const float* ln_b    = (const float*)d_in[2];
    const float* Win     = (const float*)d_in[3];
    const float* bin_    = (const float*)d_in[4];
    const float* Wout    = (const float*)d_in[5];
    const float* bout    = (const float*)d_in[6];
    const float* lre     = (const float*)d_in[7];
    const float* lim     = (const float*)d_in[8];
    const float* Bm      = (const float*)d_in[9];
    const float* cre     = (const float*)d_in[10];
    const float* cim     = (const float*)d_in[11];
    const float* Dvec    = (const float*)d_in[12];
    float* out = (float*)d_out;

    float *z, *z1, *y;
    cudaGetSymbolAddress((void**)&z,  g_z);
    cudaGetSymbolAddress((void**)&z1, g_z1);
    cudaGetSymbolAddress((void**)&y,  g_y);

    // 1. FIR taps
    kgen_kernel<<<NC, NTAPS>>>(lre, lim, Bm, cre, cim);

    // 2. LayerNorm
    ln_kernel<<<M_ROWS, 128>>>(x, ln_g, ln_b);

    // 3. in-projection: z1 = z @ Win + bin
    sgemm_kernel<0><<<dim3(4, 256), 256>>>(z, Win, bin_, nullptr, z1);

    // 4. bidirectional FIR + D skip
    fir_kernel<<<dim3(L_SEQ / 128, NC, B_SZ), 128>>>(Dvec);

    // 5. out-projection + gelu + residual -> d_out
    sgemm_kernel<1><<<dim3(4, 256), 256>>>(y, Wout, bout, x, out);
}

// round 6
// speedup vs baseline: 2.6589x; 2.6589x over previous
#include <cuda_runtime.h>
#include <cuda_bf16.h>
#include <math.h>
#include <stdint.h>

// Problem constants
#define B_SZ   8
#define L_SEQ  4096
#define D_MODEL 512
#define NC     128
#define NSTATE 64
#define NTAPS  32
#define M_ROWS (B_SZ * L_SEQ)   // 32768

// Scratch
__device__ float g_z  [M_ROWS * D_MODEL];
__device__ float g_z1 [M_ROWS * D_MODEL];
__device__ float g_y  [M_ROWS * D_MODEL];
__device__ float g_k  [NC * NTAPS];
__device__ float g_wti[D_MODEL * D_MODEL];  // Win^T, tf32-rounded
__device__ float g_wto[D_MODEL * D_MODEL];  // Wout^T, tf32-rounded

// ---------------------------------------------------------------------------
// Helpers
// ---------------------------------------------------------------------------
__device__ __forceinline__ float to_tf32(float f) {
    uint32_t u;
    asm("cvt.rna.tf32.f32 %0, %1;" : "=r"(u) : "f"(f));
    return __uint_as_float(u);
}
__device__ __forceinline__ uint32_t smem_u32(const void* p) {
    uint32_t a;
    asm("{ .reg .u64 t; cvta.to.shared.u64 t, %1; cvt.u32.u64 %0, t; }" : "=r"(a) : "l"(p));
    return a;
}
__device__ __forceinline__ void cp16(uint32_t dst, const void* src) {
    asm volatile("cp.async.cg.shared.global [%0], [%1], 16;" :: "r"(dst), "l"(src));
}
#define CP_COMMIT() asm volatile("cp.async.commit_group;" ::: "memory")
#define CP_WAIT(n)  asm volatile("cp.async.wait_group %0;" :: "n"(n) : "memory")

// m16n8k8 tf32 warp MMA (sm_80+; legal on base sm_103 target)
__device__ __forceinline__ void mma_tf32(float c[4],
                                         float a0, float a1, float a2, float a3,
                                         float b0, float b1)
{
    asm volatile(
        "mma.sync.aligned.m16n8k8.row.col.f32.tf32.tf32.f32 "
        "{%0,%1,%2,%3}, {%4,%5,%6,%7}, {%8,%9}, {%0,%1,%2,%3};"
        : "+f"(c[0]), "+f"(c[1]), "+f"(c[2]), "+f"(c[3])
        : "r"(__float_as_uint(a0)), "r"(__float_as_uint(a1)),
          "r"(__float_as_uint(a2)), "r"(__float_as_uint(a3)),
          "r"(__float_as_uint(b0)), "r"(__float_as_uint(b1)));
}

// f32x2 packed math
__device__ __forceinline__ uint64_t pk2(float a, float b) {
    uint64_t r; asm("mov.b64 %0, {%1, %2};" : "=l"(r) : "f"(a), "f"(b)); return r;
}
__device__ __forceinline__ void upk2(uint64_t v, float& a, float& b) {
    asm("mov.b64 {%0, %1}, %2;" : "=f"(a), "=f"(b) : "l"(v));
}
__device__ __forceinline__ uint64_t addx2(uint64_t a, uint64_t b) {
    uint64_t r; asm("add.rn.f32x2 %0, %1, %2;" : "=l"(r) : "l"(a), "l"(b)); return r;
}
__device__ __forceinline__ uint64_t mulx2(uint64_t a, uint64_t b) {
    uint64_t r; asm("mul.rn.f32x2 %0, %1, %2;" : "=l"(r) : "l"(a), "l"(b)); return r;
}
__device__ __forceinline__ uint64_t fmax2(uint64_t a, uint64_t b, uint64_t c) {
    uint64_t r; asm("fma.rn.f32x2 %0, %1, %2, %3;" : "=l"(r) : "l"(a), "l"(b), "l"(c)); return r;
}

// ---------------------------------------------------------------------------
// Tap generation
// ---------------------------------------------------------------------------
__global__ void kgen_kernel(const float* __restrict__ lre, const float* __restrict__ lim,
                            const float* __restrict__ Bm,  const float* __restrict__ cre,
                            const float* __restrict__ cim)
{
    int c = blockIdx.x;
    int tau = threadIdx.x;
    float ft = (float)tau;
    float acc = 0.0f;
    #pragma unroll 8
    for (int n = 0; n < NSTATE; n++) {
        int idx = c * NSTATE + n;
        float re = lre[idx], im = lim[idx], bn = Bm[idx];
        float cr = cre[idx] * bn, ci = cim[idx] * bn;
        float s, co;
        sincosf(im * ft, &s, &co);
        acc += expf(re * ft) * (cr * co - ci * s);
    }
    g_k[c * NTAPS + tau] = acc;
}

// ---------------------------------------------------------------------------
// Weight transpose + tf32 RNA round: Wt[n][k] = rna(W[k][n])
// ---------------------------------------------------------------------------
__global__ void wtrans_kernel(const float* __restrict__ W, float* __restrict__ Wt)
{
    __shared__ float tile[32][33];
    int k0 = blockIdx.y * 32, n0 = blockIdx.x * 32;
    int tx = threadIdx.x, ty = threadIdx.y;    // 32 x 8
    #pragma unroll
    for (int j = 0; j < 32; j += 8)
        tile[ty + j][tx] = W[(size_t)(k0 + ty + j) * D_MODEL + n0 + tx];
    __syncthreads();
    #pragma unroll
    for (int j = 0; j < 32; j += 8)
        Wt[(size_t)(n0 + ty + j) * D_MODEL + k0 + tx] = to_tf32(tile[tx][ty + j]);
}

// ---------------------------------------------------------------------------
// LayerNorm -> tf32-rounded z
// ---------------------------------------------------------------------------
__global__ void ln_kernel(const float* __restrict__ x, const float* __restrict__ gamma,
                          const float* __restrict__ beta)
{
    int row = blockIdx.x;
    int tid = threadIdx.x;
    const float4* xr = (const float4*)(x + (size_t)row * D_MODEL);
    float4 v = xr[tid];
    float s  = v.x + v.y + v.z + v.w;
    float sq = v.x*v.x + v.y*v.y + v.z*v.z + v.w*v.w;
    #pragma unroll
    for (int off = 16; off > 0; off >>= 1) {
        s  += __shfl_xor_sync(0xFFFFFFFFu, s,  off);
        sq += __shfl_xor_sync(0xFFFFFFFFu, sq, off);
    }
    __shared__ float ss[4], ssq[4];
    int warp = tid >> 5, lane = tid & 31;
    if (lane == 0) { ss[warp] = s; ssq[warp] = sq; }
    __syncthreads();
    float tots = ss[0] + ss[1] + ss[2] + ss[3];
    float totq = ssq[0] + ssq[1] + ssq[2] + ssq[3];
    float mu  = tots * (1.0f / D_MODEL);
    float var = totq * (1.0f / D_MODEL) - mu * mu;
    float inv = rsqrtf(var + 1e-5f);
    float4 gg = ((const float4*)gamma)[tid];
    float4 bb = ((const float4*)beta)[tid];
    float4 o;
    o.x = to_tf32((v.x - mu) * inv * gg.x + bb.x);
    o.y = to_tf32((v.y - mu) * inv * gg.y + bb.y);
    o.z = to_tf32((v.z - mu) * inv * gg.z + bb.z);
    o.w = to_tf32((v.w - mu) * inv * gg.w + bb.w);
    ((float4*)(g_z + (size_t)row * D_MODEL))[tid] = o;
}

// ---------------------------------------------------------------------------
// Warp-MMA tf32 GEMM: C[M,512] = A[M,512] @ Bt[512,512]^T + bias (+gelu+resid)
// CTA tile 128x128, BK=32, 8 warps (2m x 4n), warp tile 64x32, m16n8k8.
// cp.async double-buffered smem, XOR-swizzled (group ^ row&7), 128B pitch.
// ---------------------------------------------------------------------------
__device__ __forceinline__ float gelu_exact(float v) {
    return 0.5f * v * (1.0f + erff(v * 0.70710678118654752f));
}

#define TILE_BYTES 16384                // 128 rows x 128B
#define GEMM_SMEM  (4 * TILE_BYTES)     // A0,B0,A1,B1

__device__ __forceinline__ void stage_cp(const float* __restrict__ src, uint32_t sbuf,
                                         int row0, int k0, int tid)
{
    #pragma unroll
    for (int i = 0; i < 4; i++) {
        int idx = tid + i * 256;          // 0..1023
        int row = idx >> 3, c4 = idx & 7;
        const float* g = src + (((size_t)(row0 + row)) << 9) + k0 + (c4 << 2);
        uint32_t dst = sbuf + row * 128 + ((c4 ^ (row & 7)) << 4);
        cp16(dst, g);
    }
}

template<int EPI>
__global__ __launch_bounds__(256, 2)
void gemm_mma(const float* __restrict__ A, const float* __restrict__ Bt,
              const float* __restrict__ bias, const float* __restrict__ resid,
              float* __restrict__ C)
{
    extern __shared__ __align__(16) char sm[];
    const char* sA[2] = { sm,                  sm + 2 * TILE_BYTES };
    const char* sB[2] = { sm + TILE_BYTES,     sm + 3 * TILE_BYTES };
    uint32_t uA[2] = { smem_u32(sm),                  smem_u32(sm + 2 * TILE_BYTES) };
    uint32_t uB[2] = { smem_u32(sm + TILE_BYTES),     smem_u32(sm + 3 * TILE_BYTES) };

    int tid = threadIdx.x;
    int lane = tid & 31;
    int wid  = tid >> 5;
    int wm = wid >> 2;       // 0..1
    int wn = wid & 3;        // 0..3
    int g  = lane >> 2;      // 0..7
    int t4 = lane & 3;       // 0..3

    int bn = blockIdx.x, bm = blockIdx.y;
    int rowA = bm * 128, rowB = bn * 128;

    float acc[4][4][4];
    #pragma unroll
    for (int mt = 0; mt < 4; mt++)
        #pragma unroll
        for (int nt = 0; nt < 4; nt++)
            #pragma unroll
            for (int q = 0; q < 4; q++) acc[mt][nt][q] = 0.0f;

    // prologue
    stage_cp(A,  uA[0], rowA, 0, tid);
    stage_cp(Bt, uB[0], rowB, 0, tid);
    CP_COMMIT();

    #pragma unroll 1
    for (int s = 0; s < 16; s++) {
        int b = s & 1;
        if (s + 1 < 16) {
            stage_cp(A,  uA[b ^ 1], rowA, (s + 1) * 32, tid);
            stage_cp(Bt, uB[b ^ 1], rowB, (s + 1) * 32, tid);
            CP_COMMIT();
            CP_WAIT(1);
        } else {
            CP_WAIT(0);
        }
        __syncthreads();

        const char* cA = sA[b];
        const char* cB = sB[b];
        #pragma unroll
        for (int ks = 0; ks < 4; ks++) {
            uint32_t go0 = ((uint32_t)((2 * ks)     ^ g) << 4) + ((uint32_t)t4 << 2);
            uint32_t go1 = ((uint32_t)((2 * ks + 1) ^ g) << 4) + ((uint32_t)t4 << 2);
            float af[4][4];
            #pragma unroll
            for (int mt = 0; mt < 4; mt++) {
                const char* rp = cA + (wm * 64 + mt * 16 + g) * 128;
                af[mt][0] = *(const float*)(rp + go0);
                af[mt][1] = *(const float*)(rp + 8 * 128 + go0);
                af[mt][2] = *(const float*)(rp + go1);
                af[mt][3] = *(const float*)(rp + 8 * 128 + go1);
            }
            float bf[4][2];
            #pragma unroll
            for (int nt = 0; nt < 4; nt++) {
                const char* rp = cB + (wn * 32 + nt * 8 + g) * 128;
                bf[nt][0] = *(const float*)(rp + go0);
                bf[nt][1] = *(const float*)(rp + go1);
            }
            #pragma unroll
            for (int mt = 0; mt < 4; mt++)
                #pragma unroll
                for (int nt = 0; nt < 4; nt++)
                    mma_tf32(acc[mt][nt], af[mt][0], af[mt][1], af[mt][2], af[mt][3],
                             bf[nt][0], bf[nt][1]);
        }
        __syncthreads();
    }

    // epilogue
    #pragma unroll
    for (int mt = 0; mt < 4; mt++) {
        size_t r0 = (size_t)rowA + wm * 64 + mt * 16 + g;
        size_t r1 = r0 + 8;
        #pragma unroll
        for (int nt = 0; nt < 4; nt++) {
            int col = bn * 128 + wn * 32 + nt * 8 + 2 * t4;
            float b0 = bias[col], b1 = bias[col + 1];
            float v0 = acc[mt][nt][0] + b0;
            float v1 = acc[mt][nt][1] + b1;
            float v2 = acc[mt][nt][2] + b0;
            float v3 = acc[mt][nt][3] + b1;
            if (EPI == 1) {
                const float* rr0 = resid + r0 * D_MODEL + col;
                const float* rr1 = resid + r1 * D_MODEL + col;
                v0 = rr0[0] + gelu_exact(v0);
                v1 = rr0[1] + gelu_exact(v1);
                v2 = rr1[0] + gelu_exact(v2);
                v3 = rr1[1] + gelu_exact(v3);
            }
            *(float2*)(C + r0 * D_MODEL + col) = make_float2(v0, v1);
            *(float2*)(C + r1 * D_MODEL + col) = make_float2(v2, v3);
        }
    }
}

// ---------------------------------------------------------------------------
// Bidirectional 32-tap FIR + D skip. R=4 consecutive outputs/thread,
// sliding register windows, f32x2 math, swizzled smem. Output tf32-rounded.
// ---------------------------------------------------------------------------
#define FT_BLK 512
#define SU(i) su[(i) + ((i) >> 3)]

__global__ __launch_bounds__(128)
void fir_kernel(const float* __restrict__ Dvec)
{
    int c  = blockIdx.y;
    int b  = blockIdx.z;
    int t0 = blockIdx.x * FT_BLK;
    int tid = threadIdx.x;

    __shared__ float4 su[649];   // 577 logical slots, swizzled
    __shared__ float  sk[NTAPS];

    const float4* u4 = (const float4*)g_z1;
    for (int i = tid; i < 577; i += 128) {
        int t = t0 - 32 + i;
        float4 v = make_float4(0.f, 0.f, 0.f, 0.f);
        if (t >= 0 && t < L_SEQ) v = u4[((size_t)b * L_SEQ + t) * NC + c];
        SU(i) = v;
    }
    if (tid < NTAPS) sk[tid] = g_k[c * NTAPS + tid];
    __syncthreads();

    int w = tid * 4;
    float4 F[4], Bw[4];
    #pragma unroll
    for (int r = 0; r < 4; r++) { F[r] = SU(w + 32 + r); Bw[r] = SU(w + 33 + r); }

    float dv = Dvec[c];
    uint64_t dv2 = pk2(dv, dv);
    uint64_t aL[4], aH[4];
    #pragma unroll
    for (int r = 0; r < 4; r++) {
        aL[r] = mulx2(dv2, pk2(F[r].x, F[r].y));
        aH[r] = mulx2(dv2, pk2(F[r].z, F[r].w));
    }

    #pragma unroll
    for (int tau = 0; tau < NTAPS; tau++) {
        float kt = sk[tau];
        uint64_t k2 = pk2(kt, kt);
        #pragma unroll
        for (int r = 0; r < 4; r++) {
            uint64_t sL = addx2(pk2(F[r].x, F[r].y), pk2(Bw[r].x, Bw[r].y));
            uint64_t sH = addx2(pk2(F[r].z, F[r].w), pk2(Bw[r].z, Bw[r].w));
            aL[r] = fmax2(k2, sL, aL[r]);
            aH[r] = fmax2(k2, sH, aH[r]);
        }
        #pragma unroll
        for (int r = 3; r > 0; r--) F[r] = F[r - 1];
        F[0] = SU(w + 31 - tau);
        #pragma unroll
        for (int r = 0; r < 3; r++) Bw[r] = Bw[r + 1];
        Bw[3] = SU(w + 37 + tau);
    }

    float4* y4 = (float4*)g_y;
    #pragma unroll
    for (int r = 0; r < 4; r++) {
        float4 o;
        upk2(aL[r], o.x, o.y);
        upk2(aH[r], o.z, o.w);
        o.x = to_tf32(o.x); o.y = to_tf32(o.y); o.z = to_tf32(o.z); o.w = to_tf32(o.w);
        y4[((size_t)b * L_SEQ + t0 + w + r) * NC + c] = o;
    }
}

// ---------------------------------------------------------------------------
// Launch
// ---------------------------------------------------------------------------
extern "C" void kernel_launch(void* const* d_in, const int* in_sizes, int n_in,
                              void* d_out, int out_size)
{
    const float* x    = (const float*)d_in[0];
    const float* ln_g = (const float*)d_in[1];
    const float* ln_b = (const float*)d_in[2];
    const float* Win  = (const float*)d_in[3];
    const float* bin_ = (const float*)d_in[4];
    const float* Wout = (const float*)d_in[5];
    const float* bout = (const float*)d_in[6];
    const float* lre  = (const float*)d_in[7];
    const float* lim  = (const float*)d_in[8];
    const float* Bm   = (const float*)d_in[9];
    const float* cre  = (const float*)d_in[10];
    const float* cim  = (const float*)d_in[11];
    const float* Dvec = (const float*)d_in[12];
    float* out = (float*)d_out;

    float *z, *z1, *y, *wti, *wto;
    cudaGetSymbolAddress((void**)&z,   g_z);
    cudaGetSymbolAddress((void**)&z1,  g_z1);
    cudaGetSymbolAddress((void**)&y,   g_y);
    cudaGetSymbolAddress((void**)&wti, g_wti);
    cudaGetSymbolAddress((void**)&wto, g_wto);

    cudaFuncSetAttribute(gemm_mma<0>, cudaFuncAttributeMaxDynamicSharedMemorySize, GEMM_SMEM);
    cudaFuncSetAttribute(gemm_mma<1>, cudaFuncAttributeMaxDynamicSharedMemorySize, GEMM_SMEM);

    // 1. FIR taps + transposed/rounded weights
    kgen_kernel<<<NC, NTAPS>>>(lre, lim, Bm, cre, cim);
    wtrans_kernel<<<dim3(16, 16), dim3(32, 8)>>>(Win,  wti);
    wtrans_kernel<<<dim3(16, 16), dim3(32, 8)>>>(Wout, wto);

    // 2. LayerNorm
    ln_kernel<<<M_ROWS, 128>>>(x, ln_g, ln_b);

    // 3. in-projection (tensor cores): z1 = z @ Win + bin
    gemm_mma<0><<<dim3(4, 256), 256, GEMM_SMEM>>>(z, wti, bin_, nullptr, z1);

    // 4. bidirectional FIR + D skip
    fir_kernel<<<dim3(L_SEQ / FT_BLK, NC, B_SZ), 128>>>(Dvec);

    // 5. out-projection + gelu + residual -> d_out
    gemm_mma<1><<<dim3(4, 256), 256, GEMM_SMEM>>>(y, wto, bout, x, out);
}